// round 11
// baseline (speedup 1.0000x reference)
#include <cuda_runtime.h>
#include <cuda_bf16.h>
#include <cstdint>
#include <cstddef>

#define NN 20000
#define EE 640000
#define HH 128
#define LL 10

typedef unsigned long long u64;

__device__ float g_h[(size_t)NN * HH];
__device__ float g_hagg[(size_t)NN * HH];
__device__ float g_P[(size_t)NN * HH];
__device__ float g_Q[(size_t)NN * HH];
__device__ float g_R[(size_t)NN * HH];
__device__ float g_deg[NN];
__device__ float g_zeros[HH];
__device__ __nv_bfloat16 g_eh[(size_t)EE * HH];
__device__ __nv_bfloat16 g_el[(size_t)EE * HH];
__device__ __nv_bfloat16 g_wh[4 * HH * HH];   // transposed [n][k] hi (W1c, We2, Wn1b, ee_w2)
__device__ __nv_bfloat16 g_wl[4 * HH * HH];   // transposed [n][k] lo
__device__ int g_src[EE];
__device__ int g_dst[EE];
__device__ int g_is64;

// ---------------- mma.sync / ldmatrix / cp.async macros ----------------
#define MMA_BF16(d, a, b) \
    asm volatile("mma.sync.aligned.m16n8k16.row.col.f32.bf16.bf16.f32 " \
        "{%0,%1,%2,%3}, {%4,%5,%6,%7}, {%8,%9}, {%0,%1,%2,%3};" \
        : "+f"((d)[0]), "+f"((d)[1]), "+f"((d)[2]), "+f"((d)[3]) \
        : "r"((a)[0]), "r"((a)[1]), "r"((a)[2]), "r"((a)[3]), \
          "r"((b)[0]), "r"((b)[1]))

#define LDSM4(r, addr) \
    asm volatile("ldmatrix.sync.aligned.m8n8.x4.shared.b16 {%0,%1,%2,%3}, [%4];" \
        : "=r"((r)[0]), "=r"((r)[1]), "=r"((r)[2]), "=r"((r)[3]) : "r"(addr))

#define LDSM2(r, addr) \
    asm volatile("ldmatrix.sync.aligned.m8n8.x2.shared.b16 {%0,%1}, [%2];" \
        : "=r"((r)[0]), "=r"((r)[1]) : "r"(addr))

#define CP_ASYNC16(dst, src) \
    asm volatile("cp.async.cg.shared.global [%0], [%1], 16;" :: "r"(dst), "l"(src))
#define CP_COMMIT() asm volatile("cp.async.commit_group;" ::: "memory")
#define CP_WAIT0()  asm volatile("cp.async.wait_group 0;" ::: "memory")

// ---------------- f32x2 helpers (SIMT node kernels) ----------------
__device__ __forceinline__ u64 bcast2(float x) {
    u64 r; unsigned u = __float_as_uint(x);
    asm("mov.b64 %0, {%1, %1};" : "=l"(r) : "r"(u));
    return r;
}
__device__ __forceinline__ u64 fma2(u64 a, u64 b, u64 c) {
    u64 d;
    asm("fma.rn.f32x2 %0, %1, %2, %3;" : "=l"(d) : "l"(a), "l"(b), "l"(c));
    return d;
}
__device__ __forceinline__ void unpack2(u64 v, float& x, float& y) {
    unsigned lo, hi;
    asm("mov.b64 {%0, %1}, %2;" : "=r"(lo), "=r"(hi) : "l"(v));
    x = __uint_as_float(lo); y = __uint_as_float(hi);
}
__device__ __forceinline__ void red2(float* p, float a, float b) {
    asm volatile("red.global.add.v2.f32 [%0], {%1,%2};"
                 :: "l"(p), "f"(a), "f"(b) : "memory");
}

// ---------------- bf16 pack/split helpers (bit-trick reconstruct) ----------------
__device__ __forceinline__ float2 bf2f(unsigned u) {
    return make_float2(__uint_as_float(u << 16),
                       __uint_as_float(u & 0xFFFF0000u));
}
__device__ __forceinline__ unsigned f2bf2(float a, float b) {
    __nv_bfloat162 t = __floats2bfloat162_rn(a, b);
    return *(unsigned*)&t;
}
__device__ __forceinline__ void split2(float v0, float v1, unsigned& h, unsigned& l) {
    h = f2bf2(v0, v1);
    float a0 = __uint_as_float(h << 16);
    float a1 = __uint_as_float(h & 0xFFFF0000u);
    l = f2bf2(v0 - a0, v1 - a1);
}
__device__ __forceinline__ void split_store8(const float* f,
                                             __nv_bfloat16* H, __nv_bfloat16* L) {
    unsigned h[4], l[4];
#pragma unroll
    for (int i = 0; i < 4; i++) split2(f[2 * i], f[2 * i + 1], h[i], l[i]);
    *(uint4*)H = make_uint4(h[0], h[1], h[2], h[3]);
    *(uint4*)L = make_uint4(l[0], l[1], l[2], l[3]);
}

// ---------------- SIMT tile GEMM (node-side kernels) ----------------
template<int K>
__device__ __forceinline__ void gemm_tile(const float* __restrict__ As, int AS,
                                          const float* __restrict__ Wg,
                                          float* __restrict__ Wb,
                                          u64 acc[16], int tid, int tx, int ty) {
    constexpr int CH  = (K < 32) ? K : 32;
    constexpr int NCH = K / CH;
    constexpr int LPT = (CH * HH) / (4 * 256);
    const float* ar0 = As + (ty * 4 + 0) * AS;
    const float* ar1 = ar0 + AS;
    const float* ar2 = ar1 + AS;
    const float* ar3 = ar2 + AS;
    float4 pre[LPT];
#pragma unroll
    for (int t = 0; t < LPT; t++) pre[t] = __ldg((const float4*)Wg + tid + t * 256);
#pragma unroll
    for (int t = 0; t < LPT; t++) ((float4*)Wb)[tid + t * 256] = pre[t];
#pragma unroll 1
    for (int c = 0; c < NCH; c++) {
        __syncthreads();
        if (c + 1 < NCH) {
#pragma unroll
            for (int t = 0; t < LPT; t++)
                pre[t] = __ldg((const float4*)(Wg + (size_t)(c + 1) * CH * HH) + tid + t * 256);
        }
        const float* wbase = Wb + (c & 1) * CH * HH + tx * 8;
        const int kb = c * CH;
#pragma unroll
        for (int kk = 0; kk < CH; kk++) {
            u64 p0 = bcast2(ar0[kb + kk]);
            u64 p1 = bcast2(ar1[kb + kk]);
            u64 p2 = bcast2(ar2[kb + kk]);
            u64 p3 = bcast2(ar3[kb + kk]);
            const float* wr = wbase + kk * HH;
            ulonglong2 wA = *(const ulonglong2*)(wr);
            ulonglong2 wB = *(const ulonglong2*)(wr + 4);
            acc[0]  = fma2(p0, wA.x, acc[0]);  acc[1]  = fma2(p0, wA.y, acc[1]);
            acc[2]  = fma2(p0, wB.x, acc[2]);  acc[3]  = fma2(p0, wB.y, acc[3]);
            acc[4]  = fma2(p1, wA.x, acc[4]);  acc[5]  = fma2(p1, wA.y, acc[5]);
            acc[6]  = fma2(p1, wB.x, acc[6]);  acc[7]  = fma2(p1, wB.y, acc[7]);
            acc[8]  = fma2(p2, wA.x, acc[8]);  acc[9]  = fma2(p2, wA.y, acc[9]);
            acc[10] = fma2(p2, wB.x, acc[10]); acc[11] = fma2(p2, wB.y, acc[11]);
            acc[12] = fma2(p3, wA.x, acc[12]); acc[13] = fma2(p3, wA.y, acc[13]);
            acc[14] = fma2(p3, wB.x, acc[14]); acc[15] = fma2(p3, wB.y, acc[15]);
        }
        if (c + 1 < NCH) {
#pragma unroll
            for (int t = 0; t < LPT; t++)
                ((float4*)(Wb + ((c + 1) & 1) * CH * HH))[tid + t * 256] = pre[t];
        }
    }
}

__device__ __forceinline__ void zero_acc(u64 acc[16]) {
#pragma unroll
    for (int i = 0; i < 16; i++) acc[i] = 0ull;
}

__device__ __forceinline__ void acc_finish(const u64 acc[16], const float* __restrict__ bg,
                                           int tx, float o[4][8]) {
    float4 b0 = __ldg((const float4*)(bg + tx * 8));
    float4 b1 = __ldg((const float4*)(bg + tx * 8) + 1);
#pragma unroll
    for (int i = 0; i < 4; i++) {
#pragma unroll
        for (int j = 0; j < 4; j++) unpack2(acc[i * 4 + j], o[i][2 * j], o[i][2 * j + 1]);
        o[i][0] += b0.x; o[i][1] += b0.y; o[i][2] += b0.z; o[i][3] += b0.w;
        o[i][4] += b1.x; o[i][5] += b1.y; o[i][6] += b1.z; o[i][7] += b1.w;
    }
}

// ---------------- misc ----------------
__global__ void zero_misc_kernel() {
    int i = blockIdx.x * blockDim.x + threadIdx.x;
    ((float4*)g_hagg)[i] = make_float4(0.f, 0.f, 0.f, 0.f);
    if (i < NN) g_deg[i] = 0.f;
}

__global__ void detect_idx_kernel(const int* raw) {
    if (threadIdx.x == 0) {
        int flag = 1;
#pragma unroll
        for (int t = 1; t < 16; t += 2) if (raw[t] != 0) flag = 0;
        g_is64 = flag;
    }
}

__global__ void convert_idx_kernel(const void* eidx) {
    int i = blockIdx.x * blockDim.x + threadIdx.x;
    if (i >= EE) return;
    int s, d;
    if (g_is64) {
        const long long* p = (const long long*)eidx;
        s = (int)p[i]; d = (int)p[(size_t)EE + i];
    } else {
        const int* p = (const int*)eidx;
        s = p[i]; d = p[EE + i];
    }
    g_src[i] = s; g_dst[i] = d;
    atomicAdd(&g_deg[d], 1.0f);
}

// transpose + split the 4 mma-GEMM weights: g_w*[m][n][k] = W_m[k][n]
__global__ void prep_w_kernel(const float* __restrict__ W1c,
                              const float* __restrict__ We2,
                              const float* __restrict__ Wn1b,
                              const float* __restrict__ EW2) {
    int i = blockIdx.x * 256 + threadIdx.x;
    if (i >= 4 * HH * HH) return;
    int m = i >> 14, idx = i & 16383, n = idx >> 7, k = idx & 127;
    const float* W = (m == 0) ? W1c : (m == 1) ? We2 : (m == 2) ? Wn1b : EW2;
    float v = __ldg(W + k * HH + n);
    __nv_bfloat16 h = __float2bfloat16(v);
    g_wh[i] = h;
    g_wl[i] = __float2bfloat16(v - __bfloat162float(h));
}

// ---------------- node encoder (SIMT) ----------------
__global__ void __launch_bounds__(256, 2)
node_enc_kernel(const float* __restrict__ x, const float* __restrict__ nz,
                const float* __restrict__ W1, const float* __restrict__ b1,
                const float* __restrict__ W2, const float* __restrict__ b2) {
    extern __shared__ float sm[];
    float* A   = sm;
    float* hid = sm + 64 * 20;
    float* Wb  = hid + 64 * 132;
    const int tid = threadIdx.x, tx = tid & 15, ty = tid >> 4;
    const int nb = blockIdx.x * 64;
    {
        int r = tid >> 2, c4 = tid & 3;
        float4 v = make_float4(0.f, 0.f, 0.f, 0.f);
        if (nb + r < NN) {
            float4 a = __ldg((const float4*)(x  + (size_t)(nb + r) * 16) + c4);
            float4 n = __ldg((const float4*)(nz + (size_t)(nb + r) * 16) + c4);
            v = make_float4(a.x + n.x, a.y + n.y, a.z + n.z, a.w + n.w);
        }
        *(float4*)(A + r * 20 + (c4 << 2)) = v;
    }
    __syncthreads();
    u64 acc[16]; float o[4][8];
    zero_acc(acc);
    gemm_tile<16>(A, 20, W1, Wb, acc, tid, tx, ty);
    acc_finish(acc, b1, tx, o);
    __syncthreads();
#pragma unroll
    for (int i = 0; i < 4; i++)
#pragma unroll
        for (int j = 0; j < 8; j++)
            hid[(ty * 4 + i) * 132 + tx * 8 + j] = fmaxf(o[i][j], 0.f);
    __syncthreads();
    zero_acc(acc);
    gemm_tile<128>(hid, 132, W2, Wb, acc, tid, tx, ty);
    acc_finish(acc, b2, tx, o);
#pragma unroll
    for (int i = 0; i < 4; i++) {
        int r = ty * 4 + i;
        if (nb + r < NN) {
            float* p = g_h + (size_t)(nb + r) * HH + tx * 8;
            *(float4*)p       = make_float4(o[i][0], o[i][1], o[i][2], o[i][3]);
            *(float4*)(p + 4) = make_float4(o[i][4], o[i][5], o[i][6], o[i][7]);
        }
    }
}

// ---------------- node precompute (initial, SIMT) ----------------
__global__ void __launch_bounds__(256, 2)
node_pre_kernel(const float* __restrict__ W1a, const float* __restrict__ W1b,
                const float* __restrict__ Wn1a,
                const float* __restrict__ b1, const float* __restrict__ bn1) {
    extern __shared__ float sm[];
    float* A  = sm;
    float* Wb = sm + 64 * 132;
    const int tid = threadIdx.x, tx = tid & 15, ty = tid >> 4;
    const int nb = blockIdx.x * 64;
#pragma unroll 1
    for (int t = 0; t < 8; t++) {
        int idx = tid + t * 256;
        int r = idx >> 5, c4 = idx & 31;
        float4 v = make_float4(0.f, 0.f, 0.f, 0.f);
        if (nb + r < NN) v = __ldg((const float4*)(g_h + (size_t)(nb + r) * HH) + c4);
        *(float4*)(A + r * 132 + (c4 << 2)) = v;
    }
    __syncthreads();
    u64 acc[16]; float o[4][8];
    zero_acc(acc);
    gemm_tile<128>(A, 132, W1a, Wb, acc, tid, tx, ty);
    acc_finish(acc, b1, tx, o);
#pragma unroll
    for (int i = 0; i < 4; i++) {
        int r = ty * 4 + i;
        if (nb + r < NN) {
            float* p = g_P + (size_t)(nb + r) * HH + tx * 8;
            *(float4*)p       = make_float4(o[i][0], o[i][1], o[i][2], o[i][3]);
            *(float4*)(p + 4) = make_float4(o[i][4], o[i][5], o[i][6], o[i][7]);
        }
    }
    zero_acc(acc);
    gemm_tile<128>(A, 132, W1b, Wb, acc, tid, tx, ty);
    acc_finish(acc, g_zeros, tx, o);
#pragma unroll
    for (int i = 0; i < 4; i++) {
        int r = ty * 4 + i;
        if (nb + r < NN) {
            float* p = g_Q + (size_t)(nb + r) * HH + tx * 8;
            *(float4*)p       = make_float4(o[i][0], o[i][1], o[i][2], o[i][3]);
            *(float4*)(p + 4) = make_float4(o[i][4], o[i][5], o[i][6], o[i][7]);
        }
    }
    zero_acc(acc);
    gemm_tile<128>(A, 132, Wn1a, Wb, acc, tid, tx, ty);
    acc_finish(acc, bn1, tx, o);
#pragma unroll
    for (int i = 0; i < 4; i++) {
        int r = ty * 4 + i;
        if (nb + r < NN) {
            float* p = g_R + (size_t)(nb + r) * HH + tx * 8;
            *(float4*)p       = make_float4(o[i][0], o[i][1], o[i][2], o[i][3]);
            *(float4*)(p + 4) = make_float4(o[i][4], o[i][5], o[i][6], o[i][7]);
        }
    }
}

// ---------------- mma.sync machinery (512-thread edge kernels) ----------------
#define SRDB 272
#define TILEB (128 * SRDB)          // 34816
#define OFF_EH 0
#define OFF_EL TILEB
#define OFF_XH (2 * TILEB)
#define OFF_XL (3 * TILEB)
#define OFF_WH (4 * TILEB)
#define OFF_WL (5 * TILEB)
#define OFF_RED (6 * TILEB)
#define SM_EL_TOTAL (6 * TILEB + 4096)   // 212992

#define ENC_AUX (4 * TILEB)
#define SM_EENC (4 * TILEB + 4096 + 1024)  // 144384

static __device__ __forceinline__ uint32_t smem_u32(const void* p) {
    uint32_t a;
    asm("{ .reg .u64 t; cvta.to.shared.u64 t, %1; cvt.u32.u64 %0, t; }"
        : "=r"(a) : "l"(p));
    return a;
}

// 512-thread tile stage via registers (used by encoder)
__device__ __forceinline__ void load_matp(char* dstS,
                                          const __nv_bfloat16* __restrict__ src, int tid) {
    int r = tid >> 2, q = tid & 3;
#pragma unroll
    for (int j = 0; j < 4; j++) {
        int c = q * 32 + j * 8;
        uint4 v = __ldg((const uint4*)(src + (size_t)r * HH + c));
        *(uint4*)(dstS + r * SRDB + c * 2) = v;
    }
}

// 512-thread tile stage via cp.async (caller commits/waits)
__device__ __forceinline__ void cp_matp(uint32_t dstS,
                                        const __nv_bfloat16* __restrict__ src, int tid) {
    int r = tid >> 2, q = tid & 3;
#pragma unroll
    for (int j = 0; j < 4; j++) {
        int c = q * 32 + j * 8;
        CP_ASYNC16(dstS + (uint32_t)(r * SRDB + c * 2), src + (size_t)r * HH + c);
    }
}

// 16 warps: rg = w>>2 (rows 32*rg, mi<2 of 16), cg = w&3 (cols 32*cg)
__device__ __forceinline__ void gemm_pass(float acc[2][4][4], uint32_t A, uint32_t B,
                                          int lane, int rg, int cg) {
    const uint32_t la4 = (uint32_t)((lane & 15) * SRDB + (lane >> 4) * 16);
    const uint32_t lb2 = (uint32_t)((lane & 7) * SRDB + ((lane >> 3) & 1) * 16);
#pragma unroll
    for (int kb = 0; kb < 8; kb++) {
        unsigned a[2][4], b[4][2];
#pragma unroll
        for (int mi = 0; mi < 2; mi++)
            LDSM4(a[mi], A + (32 * rg + 16 * mi) * SRDB + kb * 32 + la4);
#pragma unroll
        for (int ni = 0; ni < 4; ni++)
            LDSM2(b[ni], B + (32 * cg + 8 * ni) * SRDB + kb * 32 + lb2);
#pragma unroll
        for (int mi = 0; mi < 2; mi++)
#pragma unroll
            for (int ni = 0; ni < 4; ni++)
                MMA_BF16(acc[mi][ni], a[mi], b[ni]);
    }
}

__device__ __forceinline__ void gemm3(float acc[2][4][4],
                                      uint32_t Ah, uint32_t Al,
                                      uint32_t Bh, uint32_t Bl,
                                      int lane, int rg, int cg) {
#pragma unroll
    for (int mi = 0; mi < 2; mi++)
#pragma unroll
        for (int ni = 0; ni < 4; ni++)
#pragma unroll
            for (int q = 0; q < 4; q++) acc[mi][ni][q] = 0.f;
    gemm_pass(acc, Ah, Bh, lane, rg, cg);
    gemm_pass(acc, Ah, Bl, lane, rg, cg);
    gemm_pass(acc, Al, Bh, lane, rg, cg);
}

// ---------------- edge encoder (tensorized) ----------------
__global__ void __launch_bounds__(512, 1)
edge_enc_tc(const float* __restrict__ ea, const float* __restrict__ ez,
            const float* __restrict__ W1, const float* __restrict__ b1,
            const float* __restrict__ b2) {
    extern __shared__ char smraw[];
    char* XHs = smraw + 0;
    char* XLs = smraw + TILEB;
    char* WHs = smraw + 2 * TILEB;
    char* WLs = smraw + 3 * TILEB;
    float* W1s = (float*)(smraw + ENC_AUX);
    float* b1s = W1s + 1024;
    float* b2s = b1s + 128;
    const int tid = threadIdx.x, lane = tid & 31, w = tid >> 5;
    const int rg = w >> 2, cg = w & 3, quad = lane >> 2, tq = lane & 3;
    const int eb = blockIdx.x * 128;
    const uint32_t sb = smem_u32(smraw);

    load_matp(WHs, g_wh + 3 * 16384, tid);
    load_matp(WLs, g_wl + 3 * 16384, tid);
    if (tid < 256)      ((float4*)W1s)[tid] = __ldg((const float4*)W1 + tid);
    else if (tid < 288) ((float4*)b1s)[tid - 256] = __ldg((const float4*)b1 + (tid - 256));
    else if (tid < 320) ((float4*)b2s)[tid - 288] = __ldg((const float4*)b2 + (tid - 288));

    const int row = tid >> 2, q = tid & 3;
    float in8[8];
    {
        const float4* pa = (const float4*)(ea + (size_t)(eb + row) * 8);
        const float4* pn = (const float4*)(ez + (size_t)(eb + row) * 8);
        float4 a0 = __ldg(pa), a1 = __ldg(pa + 1);
        float4 n0 = __ldg(pn), n1 = __ldg(pn + 1);
        in8[0] = a0.x + n0.x; in8[1] = a0.y + n0.y;
        in8[2] = a0.z + n0.z; in8[3] = a0.w + n0.w;
        in8[4] = a1.x + n1.x; in8[5] = a1.y + n1.y;
        in8[6] = a1.z + n1.z; in8[7] = a1.w + n1.w;
    }
    __syncthreads();
#pragma unroll
    for (int j = 0; j < 4; j++) {
        int c0 = j * 32 + q * 8;
        float f8[8];
#pragma unroll
        for (int cc = 0; cc < 8; cc++) {
            int c = c0 + cc;
            float a = b1s[c];
#pragma unroll
            for (int k = 0; k < 8; k++) a += in8[k] * W1s[k * 128 + c];
            f8[cc] = fmaxf(a, 0.f);
        }
        split_store8(f8, (__nv_bfloat16*)(XHs + row * SRDB + c0 * 2),
                         (__nv_bfloat16*)(XLs + row * SRDB + c0 * 2));
    }
    __syncthreads();
    float acc[2][4][4];
    gemm3(acc, sb + 0, sb + TILEB, sb + 2 * TILEB, sb + 3 * TILEB, lane, rg, cg);
#pragma unroll
    for (int mi = 0; mi < 2; mi++)
#pragma unroll
        for (int h = 0; h < 2; h++) {
            int r = 32 * rg + 16 * mi + 8 * h + quad;
#pragma unroll
            for (int ni = 0; ni < 4; ni++) {
                int C = 32 * cg + 8 * ni + 2 * tq;
                float d0 = acc[mi][ni][2 * h] + b2s[C];
                float d1 = acc[mi][ni][2 * h + 1] + b2s[C + 1];
                unsigned hh, ll; split2(d0, d1, hh, ll);
                size_t base = (size_t)(eb + r) * HH + C;
                *(unsigned*)(g_eh + base) = hh;
                *(unsigned*)(g_el + base) = ll;
            }
        }
}

// ---------------- mma.sync edge layer (512 threads, cp.async pipelined) ----------------
__global__ void __launch_bounds__(512, 1)
edge_layer_tc(const float* __restrict__ be2,
              const float* __restrict__ lng, const float* __restrict__ lnb) {
    extern __shared__ char smraw[];
    char* EHs = smraw + OFF_EH;
    char* ELs = smraw + OFF_EL;
    char* XHs = smraw + OFF_XH;
    char* XLs = smraw + OFF_XL;
    float* REDf = (float*)(smraw + OFF_RED);   // 128 rows x {sum, sumsq}

    const int tid = threadIdx.x, lane = tid & 31, w = tid >> 5;
    const int rg = w >> 2, cg = w & 3, quad = lane >> 2, tq = lane & 3;
    const int eb = blockIdx.x * 128;
    const uint32_t sb = smem_u32(smraw);
    const uint32_t aEH = sb + OFF_EH, aEL = sb + OFF_EL;
    const uint32_t aXH = sb + OFF_XH, aXL = sb + OFF_XL;
    const uint32_t aWH = sb + OFF_WH, aWL = sb + OFF_WL;

    if (tid < 256) REDf[tid] = 0.f;
    cp_matp(aEH, g_eh + (size_t)eb * HH, tid);
    cp_matp(aEL, g_el + (size_t)eb * HH, tid);
    cp_matp(aWH, g_wh, tid);
    cp_matp(aWL, g_wl, tid);
    CP_COMMIT();
    CP_WAIT0();
    __syncthreads();                                   // S0

    float acc[2][4][4];

    // ---- GEMM1: U = e @ W1c ----
    gemm3(acc, aEH, aEL, aWH, aWL, lane, rg, cg);
    __syncthreads();                                   // S1: W1 reads done
    cp_matp(aWH, g_wh + 16384, tid);                   // W2 copy under epi1
    cp_matp(aWL, g_wl + 16384, tid);
    CP_COMMIT();
    // epi1: t1 = relu(U + P[dst] + Q[src]) -> XH/XL
#pragma unroll
    for (int mi = 0; mi < 2; mi++) {
#pragma unroll
        for (int h = 0; h < 2; h++) {
            int row = 32 * rg + 16 * mi + 8 * h + quad;
            int dn = g_dst[eb + row], sn = g_src[eb + row];
#pragma unroll
            for (int ni = 0; ni < 4; ni++) {
                int C = 32 * cg + 8 * ni + 2 * tq;
                float d0 = acc[mi][ni][2 * h], d1 = acc[mi][ni][2 * h + 1];
                float2 p = __ldg((const float2*)(g_P + (size_t)dn * HH + C));
                float2 q = __ldg((const float2*)(g_Q + (size_t)sn * HH + C));
                float v0 = fmaxf(d0 + p.x + q.x, 0.f);
                float v1 = fmaxf(d1 + p.y + q.y, 0.f);
                unsigned hh, ll; split2(v0, v1, hh, ll);
                *(unsigned*)(XHs + row * SRDB + C * 2) = hh;
                *(unsigned*)(XLs + row * SRDB + C * 2) = ll;
            }
        }
    }
    CP_WAIT0();
    __syncthreads();                                   // S2: X + W2 ready

    // ---- GEMM2: V = t1 @ We2 ----
    gemm3(acc, aXH, aXL, aWH, aWL, lane, rg, cg);
    __syncthreads();                                   // S3: X/W2 reads done
    cp_matp(aWH, g_wh + 2 * 16384, tid);               // W3 copy under epi2
    cp_matp(aWL, g_wl + 2 * 16384, tid);
    CP_COMMIT();
    // epi2: e_new = e + V + be2 -> XH/XL ; accumulate LN sums of t = e + e_new
#pragma unroll
    for (int mi = 0; mi < 2; mi++) {
#pragma unroll
        for (int h = 0; h < 2; h++) {
            int row = 32 * rg + 16 * mi + 8 * h + quad;
            float s = 0.f, s2 = 0.f;
#pragma unroll
            for (int ni = 0; ni < 4; ni++) {
                int C = 32 * cg + 8 * ni + 2 * tq;
                float d0 = acc[mi][ni][2 * h], d1 = acc[mi][ni][2 * h + 1];
                float2 e0 = bf2f(*(unsigned*)(EHs + row * SRDB + C * 2));
                float2 e1 = bf2f(*(unsigned*)(ELs + row * SRDB + C * 2));
                float2 bb = __ldg((const float2*)(be2 + C));
                float ef0 = e0.x + e1.x, ef1 = e0.y + e1.y;
                float v0 = ef0 + d0 + bb.x;
                float v1 = ef1 + d1 + bb.y;
                unsigned hh, ll; split2(v0, v1, hh, ll);
                *(unsigned*)(XHs + row * SRDB + C * 2) = hh;
                *(unsigned*)(XLs + row * SRDB + C * 2) = ll;
                float t0 = ef0 + v0, t1 = ef1 + v1;
                s += t0 + t1;
                s2 += t0 * t0 + t1 * t1;
            }
            s  += __shfl_xor_sync(0xffffffffu, s, 1);
            s  += __shfl_xor_sync(0xffffffffu, s, 2);
            s2 += __shfl_xor_sync(0xffffffffu, s2, 1);
            s2 += __shfl_xor_sync(0xffffffffu, s2, 2);
            if (tq == 0) {
                atomicAdd(REDf + row * 2, s);
                atomicAdd(REDf + row * 2 + 1, s2);
            }
        }
    }
    CP_WAIT0();
    __syncthreads();                                   // S4: X(e_new) + W3 + RED ready

    // ---- GEMM3: T = e_new @ Wn1b ; epi3: t2 = relu(T + R[dst]) ; scatter-add ----
    gemm3(acc, aXH, aXL, aWH, aWL, lane, rg, cg);
#pragma unroll
    for (int mi = 0; mi < 2; mi++) {
#pragma unroll
        for (int h = 0; h < 2; h++) {
            int row = 32 * rg + 16 * mi + 8 * h + quad;
            int dn = g_dst[eb + row];
#pragma unroll
            for (int ni = 0; ni < 4; ni++) {
                int C = 32 * cg + 8 * ni + 2 * tq;
                float d0 = acc[mi][ni][2 * h], d1 = acc[mi][ni][2 * h + 1];
                float2 rr = __ldg((const float2*)(g_R + (size_t)dn * HH + C));
                red2(g_hagg + (size_t)dn * HH + C,
                     fmaxf(d0 + rr.x, 0.f), fmaxf(d1 + rr.y, 0.f));
            }
        }
    }

    // ---- edge LN: e_out = LN(e + e_new) -> g_eh/g_el (sums precomputed) ----
    {
        int r2 = tid >> 2, q = tid & 3;
        float sum = REDf[r2 * 2], sq = REDf[r2 * 2 + 1];
        float m = sum * (1.f / HH);
        float var = sq * (1.f / HH) - m * m;
        float inv = rsqrtf(var + 1e-5f);
#pragma unroll
        for (int j = 0; j < 4; j++) {
            int c = q * 32 + j * 8;
            uint4 aH = *(uint4*)(EHs + r2 * SRDB + c * 2);
            uint4 aL = *(uint4*)(ELs + r2 * SRDB + c * 2);
            uint4 xH = *(uint4*)(XHs + r2 * SRDB + c * 2);
            uint4 xL = *(uint4*)(XLs + r2 * SRDB + c * 2);
            unsigned au[4] = {aH.x, aH.y, aH.z, aH.w};
            unsigned bu[4] = {aL.x, aL.y, aL.z, aL.w};
            unsigned cu[4] = {xH.x, xH.y, xH.z, xH.w};
            unsigned du[4] = {xL.x, xL.y, xL.z, xL.w};
            float4 g0 = __ldg((const float4*)(lng + c));
            float4 g1 = __ldg((const float4*)(lng + c) + 1);
            float4 b0 = __ldg((const float4*)(lnb + c));
            float4 b1 = __ldg((const float4*)(lnb + c) + 1);
            float g8[8] = {g0.x, g0.y, g0.z, g0.w, g1.x, g1.y, g1.z, g1.w};
            float b8[8] = {b0.x, b0.y, b0.z, b0.w, b1.x, b1.y, b1.z, b1.w};
            unsigned oh[4], ol[4];
#pragma unroll
            for (int t = 0; t < 4; t++) {
                float2 a = bf2f(au[t]), b = bf2f(bu[t]);
                float2 cc = bf2f(cu[t]), d = bf2f(du[t]);
                float f0 = ((a.x + b.x + cc.x + d.x) - m) * inv * g8[2 * t] + b8[2 * t];
                float f1 = ((a.y + b.y + cc.y + d.y) - m) * inv * g8[2 * t + 1] + b8[2 * t + 1];
                split2(f0, f1, oh[t], ol[t]);
            }
            size_t gbase = (size_t)(eb + r2) * HH + c;
            *(uint4*)(g_eh + gbase) = make_uint4(oh[0], oh[1], oh[2], oh[3]);
            *(uint4*)(g_el + gbase) = make_uint4(ol[0], ol[1], ol[2], ol[3]);
        }
    }
}

// ---------------- fused node post(l) + pre(l+1) ----------------
__global__ void __launch_bounds__(256, 2)
node_fuse_kernel(const float* __restrict__ Wn2, const float* __restrict__ bn2,
                 const float* __restrict__ lg, const float* __restrict__ lb,
                 const float* __restrict__ W1a, const float* __restrict__ W1b,
                 const float* __restrict__ Wn1a,
                 const float* __restrict__ b1, const float* __restrict__ bn1) {
    extern __shared__ float sm[];
    float* A  = sm;
    float* Wb = sm + 64 * 132;
    const int tid = threadIdx.x, tx = tid & 15, ty = tid >> 4;
    const int nb = blockIdx.x * 64;
#pragma unroll 1
    for (int t = 0; t < 8; t++) {
        int idx = tid + t * 256;
        int r = idx >> 5, c4 = idx & 31;
        float4 v = make_float4(0.f, 0.f, 0.f, 0.f);
        if (nb + r < NN) v = *(const float4*)(g_hagg + (size_t)(nb + r) * HH + (c4 << 2));
        *(float4*)(A + r * 132 + (c4 << 2)) = v;
    }
    __syncthreads();
    u64 acc[16]; float o[4][8];
    zero_acc(acc);
    gemm_tile<128>(A, 132, Wn2, Wb, acc, tid, tx, ty);
    acc_finish(acc, g_zeros, tx, o);

    float4 bn0 = __ldg((const float4*)(bn2 + tx * 8));
    float4 bn1v = __ldg((const float4*)(bn2 + tx * 8) + 1);
    float4 lg0 = __ldg((const float4*)(lg + tx * 8));
    float4 lg1 = __ldg((const float4*)(lg + tx * 8) + 1);
    float4 lb0 = __ldg((const float4*)(lb + tx * 8));
    float4 lb1 = __ldg((const float4*)(lb + tx * 8) + 1);

#pragma unroll
    for (int i = 0; i < 4; i++) {
        int gi = nb + ty * 4 + i;
        if (gi < NN) {
            float deg = g_deg[gi];
            const float* hp = g_h + (size_t)gi * HH + tx * 8;
            float bnv[8] = {bn0.x, bn0.y, bn0.z, bn0.w, bn1v.x, bn1v.y, bn1v.z, bn1v.w};
            float v[8];
#pragma unroll
            for (int j = 0; j < 8; j++)
                v[j] = hp[j] * (1.f + deg) + o[i][j] + deg * bnv[j];
            float s = 0.f;
#pragma unroll
            for (int j = 0; j < 8; j++) s += v[j];
            s += __shfl_xor_sync(0xffffffffu, s, 1);
            s += __shfl_xor_sync(0xffffffffu, s, 2);
            s += __shfl_xor_sync(0xffffffffu, s, 4);
            s += __shfl_xor_sync(0xffffffffu, s, 8);
            float m = s * (1.f / HH);
            float s2 = 0.f;
#pragma unroll
            for (int j = 0; j < 8; j++) { float d = v[j] - m; s2 += d * d; }
            s2 += __shfl_xor_sync(0xffffffffu, s2, 1);
            s2 += __shfl_xor_sync(0xffffffffu, s2, 2);
            s2 += __shfl_xor_sync(0xffffffffu, s2, 4);
            s2 += __shfl_xor_sync(0xffffffffu, s2, 8);
            float inv = rsqrtf(s2 * (1.f / HH) + 1e-5f);
            float gv[8] = {lg0.x, lg0.y, lg0.z, lg0.w, lg1.x, lg1.y, lg1.z, lg1.w};
            float bv[8] = {lb0.x, lb0.y, lb0.z, lb0.w, lb1.x, lb1.y, lb1.z, lb1.w};
            float* po = g_h + (size_t)gi * HH + tx * 8;
            float* pa = A + (ty * 4 + i) * 132 + tx * 8;
#pragma unroll
            for (int j = 0; j < 8; j++) {
                float hn = (v[j] - m) * inv * gv[j] + bv[j];
                po[j] = hn;
                pa[j] = hn;
            }
            float4 z = make_float4(0.f, 0.f, 0.f, 0.f);
            float4* pz = (float4*)(g_hagg + (size_t)gi * HH + tx * 8);
            pz[0] = z; pz[1] = z;
        }
    }
    // pre(l+1): P, Q, R from h_new already in A (gemm_tile's first sync orders A writes)
    zero_acc(acc);
    gemm_tile<128>(A, 132, W1a, Wb, acc, tid, tx, ty);
    acc_finish(acc, b1, tx, o);
#pragma unroll
    for (int i = 0; i < 4; i++) {
        int r = ty * 4 + i;
        if (nb + r < NN) {
            float* p = g_P + (size_t)(nb + r) * HH + tx * 8;
            *(float4*)p       = make_float4(o[i][0], o[i][1], o[i][2], o[i][3]);
            *(float4*)(p + 4) = make_float4(o[i][4], o[i][5], o[i][6], o[i][7]);
        }
    }
    zero_acc(acc);
    gemm_tile<128>(A, 132, W1b, Wb, acc, tid, tx, ty);
    acc_finish(acc, g_zeros, tx, o);
#pragma unroll
    for (int i = 0; i < 4; i++) {
        int r = ty * 4 + i;
        if (nb + r < NN) {
            float* p = g_Q + (size_t)(nb + r) * HH + tx * 8;
            *(float4*)p       = make_float4(o[i][0], o[i][1], o[i][2], o[i][3]);
            *(float4*)(p + 4) = make_float4(o[i][4], o[i][5], o[i][6], o[i][7]);
        }
    }
    zero_acc(acc);
    gemm_tile<128>(A, 132, Wn1a, Wb, acc, tid, tx, ty);
    acc_finish(acc, bn1, tx, o);
#pragma unroll
    for (int i = 0; i < 4; i++) {
        int r = ty * 4 + i;
        if (nb + r < NN) {
            float* p = g_R + (size_t)(nb + r) * HH + tx * 8;
            *(float4*)p       = make_float4(o[i][0], o[i][1], o[i][2], o[i][3]);
            *(float4*)(p + 4) = make_float4(o[i][4], o[i][5], o[i][6], o[i][7]);
        }
    }
}

__global__ void __launch_bounds__(256, 2)
decoder_kernel(const float* __restrict__ W1, const float* __restrict__ b1,
               const float* __restrict__ W2, const float* __restrict__ b2,
               const float* __restrict__ nz, float* __restrict__ out) {
    extern __shared__ float sm[];
    float* A   = sm;
    float* hid = sm + 64 * 132;
    float* Wb  = hid + 64 * 132;
    float* W2s = Wb + 2 * 32 * HH;
    const int tid = threadIdx.x, tx = tid & 15, ty = tid >> 4;
    const int nb = blockIdx.x * 64;
#pragma unroll 1
    for (int t = 0; t < 8; t++) {
        int idx = tid + t * 256;
        int r = idx >> 5, c4 = idx & 31;
        float4 v = make_float4(0.f, 0.f, 0.f, 0.f);
        if (nb + r < NN) v = __ldg((const float4*)(g_h + (size_t)(nb + r) * HH) + c4);
        *(float4*)(A + r * 132 + (c4 << 2)) = v;
    }
    if (tid < 256) W2s[tid] = __ldg(W2 + tid);
    __syncthreads();
    u64 acc[16]; float o[4][8];
    zero_acc(acc);
    gemm_tile<128>(A, 132, W1, Wb, acc, tid, tx, ty);
    acc_finish(acc, b1, tx, o);
#pragma unroll
    for (int i = 0; i < 4; i++)
#pragma unroll
        for (int j = 0; j < 8; j++)
            hid[(ty * 4 + i) * 132 + tx * 8 + j] = fmaxf(o[i][j], 0.f);
    __syncthreads();
    if (tid < 128) {
        int r = tid >> 1, c = tid & 1;
        if (nb + r < NN) {
            float s = 0.f;
            const float* hr = hid + r * 132;
#pragma unroll 8
            for (int k = 0; k < 128; k++) s += hr[k] * W2s[k * 2 + c];
            out[(size_t)(nb + r) * 2 + c] = s + __ldg(b2 + c)
                - __ldg(nz + (size_t)(nb + r) * 16 + c);
        }
    }
}

extern "C" void kernel_launch(void* const* d_in, const int* in_sizes, int n_in,
                              void* d_out, int out_size) {
    const float* x    = (const float*)d_in[0];
    const float* ea   = (const float*)d_in[1];
    const void*  eidx = d_in[2];
    const float* nz   = (const float*)d_in[3];
    const float* ez   = (const float*)d_in[4];
    const float* ne_w1 = (const float*)d_in[5],  *ne_b1 = (const float*)d_in[6];
    const float* ne_w2 = (const float*)d_in[7],  *ne_b2 = (const float*)d_in[8];
    const float* ee_w1 = (const float*)d_in[9],  *ee_b1 = (const float*)d_in[10];
    const float* ee_w2 = (const float*)d_in[11], *ee_b2 = (const float*)d_in[12];
    const float* ge_w1 = (const float*)d_in[13], *ge_b1 = (const float*)d_in[14];
    const float* ge_w2 = (const float*)d_in[15], *ge_b2 = (const float*)d_in[16];
    const float* gn_w1 = (const float*)d_in[17], *gn_b1 = (const float*)d_in[18];
    const float* gn_w2 = (const float*)d_in[19], *gn_b2 = (const float*)d_in[20];
    const float* xlg = (const float*)d_in[21], *xlb = (const float*)d_in[22];
    const float* elg = (const float*)d_in[23], *elb = (const float*)d_in[24];
    const float* d_w1 = (const float*)d_in[25], *d_b1 = (const float*)d_in[26];
    const float* d_w2 = (const float*)d_in[27], *d_b2 = (const float*)d_in[28];
    float* out = (float*)d_out;

    const int SM_NE  = (64 * 20 + 64 * 132 + 2 * 32 * HH) * 4;
    const int SM_NP  = (64 * 132 + 2 * 32 * HH) * 4;
    const int SM_DEC = (2 * 64 * 132 + 2 * 32 * HH + 256) * 4;
    cudaFuncSetAttribute(node_enc_kernel,  cudaFuncAttributeMaxDynamicSharedMemorySize, SM_NE);
    cudaFuncSetAttribute(edge_enc_tc,      cudaFuncAttributeMaxDynamicSharedMemorySize, SM_EENC);
    cudaFuncSetAttribute(node_pre_kernel,  cudaFuncAttributeMaxDynamicSharedMemorySize, SM_NP);
    cudaFuncSetAttribute(edge_layer_tc,    cudaFuncAttributeMaxDynamicSharedMemorySize, SM_EL_TOTAL);
    cudaFuncSetAttribute(node_fuse_kernel, cudaFuncAttributeMaxDynamicSharedMemorySize, SM_NP);
    cudaFuncSetAttribute(decoder_kernel,   cudaFuncAttributeMaxDynamicSharedMemorySize, SM_DEC);

    const float* W1a  = ge_w1;
    const float* W1b  = ge_w1 + 128 * HH;
    const float* W1c  = ge_w1 + 256 * HH;
    const float* Wn1a = gn_w1;
    const float* Wn1b = gn_w1 + 128 * HH;

    detect_idx_kernel<<<1, 32>>>((const int*)eidx);
    zero_misc_kernel<<<(NN * HH / 4) / 256, 256>>>();
    convert_idx_kernel<<<(EE + 255) / 256, 256>>>(eidx);
    prep_w_kernel<<<(4 * HH * HH + 255) / 256, 256>>>(W1c, ge_w2, Wn1b, ee_w2);

    node_enc_kernel<<<(NN + 63) / 64, 256, SM_NE>>>(x, nz, ne_w1, ne_b1, ne_w2, ne_b2);
    edge_enc_tc<<<EE / 128, 512, SM_EENC>>>(ea, ez, ee_w1, ee_b1, ee_b2);
    node_pre_kernel<<<(NN + 63) / 64, 256, SM_NP>>>(W1a, W1b, Wn1a, ge_b1, gn_b1);

    for (int l = 0; l < LL; l++) {
        edge_layer_tc<<<EE / 128, 512, SM_EL_TOTAL>>>(ge_b2, elg + l * HH, elb + l * HH);
        node_fuse_kernel<<<(NN + 63) / 64, 256, SM_NP>>>(gn_w2, gn_b2,
                                                         xlg + l * HH, xlb + l * HH,
                                                         W1a, W1b, Wn1a, ge_b1, gn_b1);
    }

    decoder_kernel<<<(NN + 63) / 64, 256, SM_DEC>>>(d_w1, d_b1, d_w2, d_b2, nz, out);
}

// round 12
// speedup vs baseline: 1.1860x; 1.1860x over previous
#include <cuda_runtime.h>
#include <cuda_bf16.h>
#include <cstdint>
#include <cstddef>

#define NN 20000
#define EE 640000
#define HH 128
#define LL 10

typedef unsigned long long u64;

__device__ float g_h[(size_t)NN * HH];
__device__ float g_hagg[(size_t)NN * HH];
__device__ float g_P[(size_t)NN * HH];
__device__ float g_Q[(size_t)NN * HH];
__device__ float g_R[(size_t)NN * HH];
__device__ float g_deg[NN];
__device__ float g_zeros[HH];
__device__ __nv_bfloat16 g_eh[(size_t)EE * HH];
__device__ __nv_bfloat16 g_el[(size_t)EE * HH];
__device__ __nv_bfloat16 g_wh[4 * HH * HH];   // transposed [n][k] hi (W1c, We2, Wn1b, ee_w2)
__device__ __nv_bfloat16 g_wl[4 * HH * HH];   // transposed [n][k] lo
__device__ int g_src[EE];
__device__ int g_dst[EE];
__device__ int g_is64;

// ---------------- mma.sync / ldmatrix macros ----------------
#define MMA_BF16(d, a, b) \
    asm volatile("mma.sync.aligned.m16n8k16.row.col.f32.bf16.bf16.f32 " \
        "{%0,%1,%2,%3}, {%4,%5,%6,%7}, {%8,%9}, {%0,%1,%2,%3};" \
        : "+f"((d)[0]), "+f"((d)[1]), "+f"((d)[2]), "+f"((d)[3]) \
        : "r"((a)[0]), "r"((a)[1]), "r"((a)[2]), "r"((a)[3]), \
          "r"((b)[0]), "r"((b)[1]))

#define LDSM4(r, addr) \
    asm volatile("ldmatrix.sync.aligned.m8n8.x4.shared.b16 {%0,%1,%2,%3}, [%4];" \
        : "=r"((r)[0]), "=r"((r)[1]), "=r"((r)[2]), "=r"((r)[3]) : "r"(addr))

#define LDSM2(r, addr) \
    asm volatile("ldmatrix.sync.aligned.m8n8.x2.shared.b16 {%0,%1}, [%2];" \
        : "=r"((r)[0]), "=r"((r)[1]) : "r"(addr))

// ---------------- f32x2 helpers (SIMT node kernels) ----------------
__device__ __forceinline__ u64 bcast2(float x) {
    u64 r; unsigned u = __float_as_uint(x);
    asm("mov.b64 %0, {%1, %1};" : "=l"(r) : "r"(u));
    return r;
}
__device__ __forceinline__ u64 fma2(u64 a, u64 b, u64 c) {
    u64 d;
    asm("fma.rn.f32x2 %0, %1, %2, %3;" : "=l"(d) : "l"(a), "l"(b), "l"(c));
    return d;
}
__device__ __forceinline__ void unpack2(u64 v, float& x, float& y) {
    unsigned lo, hi;
    asm("mov.b64 {%0, %1}, %2;" : "=r"(lo), "=r"(hi) : "l"(v));
    x = __uint_as_float(lo); y = __uint_as_float(hi);
}
__device__ __forceinline__ void red2(float* p, float a, float b) {
    asm volatile("red.global.add.v2.f32 [%0], {%1,%2};"
                 :: "l"(p), "f"(a), "f"(b) : "memory");
}

// ---------------- bf16 pack/split helpers (bit-trick reconstruct) ----------------
__device__ __forceinline__ float2 bf2f(unsigned u) {
    return make_float2(__uint_as_float(u << 16),
                       __uint_as_float(u & 0xFFFF0000u));
}
__device__ __forceinline__ unsigned f2bf2(float a, float b) {
    __nv_bfloat162 t = __floats2bfloat162_rn(a, b);
    return *(unsigned*)&t;
}
__device__ __forceinline__ void split2(float v0, float v1, unsigned& h, unsigned& l) {
    h = f2bf2(v0, v1);
    float a0 = __uint_as_float(h << 16);
    float a1 = __uint_as_float(h & 0xFFFF0000u);
    l = f2bf2(v0 - a0, v1 - a1);
}
__device__ __forceinline__ void split_store8(const float* f,
                                             __nv_bfloat16* H, __nv_bfloat16* L) {
    unsigned h[4], l[4];
#pragma unroll
    for (int i = 0; i < 4; i++) split2(f[2 * i], f[2 * i + 1], h[i], l[i]);
    *(uint4*)H = make_uint4(h[0], h[1], h[2], h[3]);
    *(uint4*)L = make_uint4(l[0], l[1], l[2], l[3]);
}

// ---------------- SIMT tile GEMM (node-side kernels) ----------------
template<int K>
__device__ __forceinline__ void gemm_tile(const float* __restrict__ As, int AS,
                                          const float* __restrict__ Wg,
                                          float* __restrict__ Wb,
                                          u64 acc[16], int tid, int tx, int ty) {
    constexpr int CH  = (K < 32) ? K : 32;
    constexpr int NCH = K / CH;
    constexpr int LPT = (CH * HH) / (4 * 256);
    const float* ar0 = As + (ty * 4 + 0) * AS;
    const float* ar1 = ar0 + AS;
    const float* ar2 = ar1 + AS;
    const float* ar3 = ar2 + AS;
    float4 pre[LPT];
#pragma unroll
    for (int t = 0; t < LPT; t++) pre[t] = __ldg((const float4*)Wg + tid + t * 256);
#pragma unroll
    for (int t = 0; t < LPT; t++) ((float4*)Wb)[tid + t * 256] = pre[t];
#pragma unroll 1
    for (int c = 0; c < NCH; c++) {
        __syncthreads();
        if (c + 1 < NCH) {
#pragma unroll
            for (int t = 0; t < LPT; t++)
                pre[t] = __ldg((const float4*)(Wg + (size_t)(c + 1) * CH * HH) + tid + t * 256);
        }
        const float* wbase = Wb + (c & 1) * CH * HH + tx * 8;
        const int kb = c * CH;
#pragma unroll
        for (int kk = 0; kk < CH; kk++) {
            u64 p0 = bcast2(ar0[kb + kk]);
            u64 p1 = bcast2(ar1[kb + kk]);
            u64 p2 = bcast2(ar2[kb + kk]);
            u64 p3 = bcast2(ar3[kb + kk]);
            const float* wr = wbase + kk * HH;
            ulonglong2 wA = *(const ulonglong2*)(wr);
            ulonglong2 wB = *(const ulonglong2*)(wr + 4);
            acc[0]  = fma2(p0, wA.x, acc[0]);  acc[1]  = fma2(p0, wA.y, acc[1]);
            acc[2]  = fma2(p0, wB.x, acc[2]);  acc[3]  = fma2(p0, wB.y, acc[3]);
            acc[4]  = fma2(p1, wA.x, acc[4]);  acc[5]  = fma2(p1, wA.y, acc[5]);
            acc[6]  = fma2(p1, wB.x, acc[6]);  acc[7]  = fma2(p1, wB.y, acc[7]);
            acc[8]  = fma2(p2, wA.x, acc[8]);  acc[9]  = fma2(p2, wA.y, acc[9]);
            acc[10] = fma2(p2, wB.x, acc[10]); acc[11] = fma2(p2, wB.y, acc[11]);
            acc[12] = fma2(p3, wA.x, acc[12]); acc[13] = fma2(p3, wA.y, acc[13]);
            acc[14] = fma2(p3, wB.x, acc[14]); acc[15] = fma2(p3, wB.y, acc[15]);
        }
        if (c + 1 < NCH) {
#pragma unroll
            for (int t = 0; t < LPT; t++)
                ((float4*)(Wb + ((c + 1) & 1) * CH * HH))[tid + t * 256] = pre[t];
        }
    }
}

__device__ __forceinline__ void zero_acc(u64 acc[16]) {
#pragma unroll
    for (int i = 0; i < 16; i++) acc[i] = 0ull;
}

__device__ __forceinline__ void acc_finish(const u64 acc[16], const float* __restrict__ bg,
                                           int tx, float o[4][8]) {
    float4 b0 = __ldg((const float4*)(bg + tx * 8));
    float4 b1 = __ldg((const float4*)(bg + tx * 8) + 1);
#pragma unroll
    for (int i = 0; i < 4; i++) {
#pragma unroll
        for (int j = 0; j < 4; j++) unpack2(acc[i * 4 + j], o[i][2 * j], o[i][2 * j + 1]);
        o[i][0] += b0.x; o[i][1] += b0.y; o[i][2] += b0.z; o[i][3] += b0.w;
        o[i][4] += b1.x; o[i][5] += b1.y; o[i][6] += b1.z; o[i][7] += b1.w;
    }
}

// ---------------- misc ----------------
__global__ void zero_misc_kernel() {
    int i = blockIdx.x * blockDim.x + threadIdx.x;
    ((float4*)g_hagg)[i] = make_float4(0.f, 0.f, 0.f, 0.f);
    if (i < NN) g_deg[i] = 0.f;
}

__global__ void detect_idx_kernel(const int* raw) {
    if (threadIdx.x == 0) {
        int flag = 1;
#pragma unroll
        for (int t = 1; t < 16; t += 2) if (raw[t] != 0) flag = 0;
        g_is64 = flag;
    }
}

__global__ void convert_idx_kernel(const void* eidx) {
    int i = blockIdx.x * blockDim.x + threadIdx.x;
    if (i >= EE) return;
    int s, d;
    if (g_is64) {
        const long long* p = (const long long*)eidx;
        s = (int)p[i]; d = (int)p[(size_t)EE + i];
    } else {
        const int* p = (const int*)eidx;
        s = p[i]; d = p[EE + i];
    }
    g_src[i] = s; g_dst[i] = d;
    atomicAdd(&g_deg[d], 1.0f);
}

// transpose + split the 4 mma-GEMM weights: g_w*[m][n][k] = W_m[k][n]
__global__ void prep_w_kernel(const float* __restrict__ W1c,
                              const float* __restrict__ We2,
                              const float* __restrict__ Wn1b,
                              const float* __restrict__ EW2) {
    int i = blockIdx.x * 256 + threadIdx.x;
    if (i >= 4 * HH * HH) return;
    int m = i >> 14, idx = i & 16383, n = idx >> 7, k = idx & 127;
    const float* W = (m == 0) ? W1c : (m == 1) ? We2 : (m == 2) ? Wn1b : EW2;
    float v = __ldg(W + k * HH + n);
    __nv_bfloat16 h = __float2bfloat16(v);
    g_wh[i] = h;
    g_wl[i] = __float2bfloat16(v - __bfloat162float(h));
}

// ---------------- node encoder (SIMT) ----------------
__global__ void __launch_bounds__(256, 2)
node_enc_kernel(const float* __restrict__ x, const float* __restrict__ nz,
                const float* __restrict__ W1, const float* __restrict__ b1,
                const float* __restrict__ W2, const float* __restrict__ b2) {
    extern __shared__ float sm[];
    float* A   = sm;
    float* hid = sm + 64 * 20;
    float* Wb  = hid + 64 * 132;
    const int tid = threadIdx.x, tx = tid & 15, ty = tid >> 4;
    const int nb = blockIdx.x * 64;
    {
        int r = tid >> 2, c4 = tid & 3;
        float4 v = make_float4(0.f, 0.f, 0.f, 0.f);
        if (nb + r < NN) {
            float4 a = __ldg((const float4*)(x  + (size_t)(nb + r) * 16) + c4);
            float4 n = __ldg((const float4*)(nz + (size_t)(nb + r) * 16) + c4);
            v = make_float4(a.x + n.x, a.y + n.y, a.z + n.z, a.w + n.w);
        }
        *(float4*)(A + r * 20 + (c4 << 2)) = v;
    }
    __syncthreads();
    u64 acc[16]; float o[4][8];
    zero_acc(acc);
    gemm_tile<16>(A, 20, W1, Wb, acc, tid, tx, ty);
    acc_finish(acc, b1, tx, o);
    __syncthreads();
#pragma unroll
    for (int i = 0; i < 4; i++)
#pragma unroll
        for (int j = 0; j < 8; j++)
            hid[(ty * 4 + i) * 132 + tx * 8 + j] = fmaxf(o[i][j], 0.f);
    __syncthreads();
    zero_acc(acc);
    gemm_tile<128>(hid, 132, W2, Wb, acc, tid, tx, ty);
    acc_finish(acc, b2, tx, o);
#pragma unroll
    for (int i = 0; i < 4; i++) {
        int r = ty * 4 + i;
        if (nb + r < NN) {
            float* p = g_h + (size_t)(nb + r) * HH + tx * 8;
            *(float4*)p       = make_float4(o[i][0], o[i][1], o[i][2], o[i][3]);
            *(float4*)(p + 4) = make_float4(o[i][4], o[i][5], o[i][6], o[i][7]);
        }
    }
}

// ---------------- node precompute (initial, SIMT) ----------------
__global__ void __launch_bounds__(256, 2)
node_pre_kernel(const float* __restrict__ W1a, const float* __restrict__ W1b,
                const float* __restrict__ Wn1a,
                const float* __restrict__ b1, const float* __restrict__ bn1) {
    extern __shared__ float sm[];
    float* A  = sm;
    float* Wb = sm + 64 * 132;
    const int tid = threadIdx.x, tx = tid & 15, ty = tid >> 4;
    const int nb = blockIdx.x * 64;
#pragma unroll 1
    for (int t = 0; t < 8; t++) {
        int idx = tid + t * 256;
        int r = idx >> 5, c4 = idx & 31;
        float4 v = make_float4(0.f, 0.f, 0.f, 0.f);
        if (nb + r < NN) v = __ldg((const float4*)(g_h + (size_t)(nb + r) * HH) + c4);
        *(float4*)(A + r * 132 + (c4 << 2)) = v;
    }
    __syncthreads();
    u64 acc[16]; float o[4][8];
    zero_acc(acc);
    gemm_tile<128>(A, 132, W1a, Wb, acc, tid, tx, ty);
    acc_finish(acc, b1, tx, o);
#pragma unroll
    for (int i = 0; i < 4; i++) {
        int r = ty * 4 + i;
        if (nb + r < NN) {
            float* p = g_P + (size_t)(nb + r) * HH + tx * 8;
            *(float4*)p       = make_float4(o[i][0], o[i][1], o[i][2], o[i][3]);
            *(float4*)(p + 4) = make_float4(o[i][4], o[i][5], o[i][6], o[i][7]);
        }
    }
    zero_acc(acc);
    gemm_tile<128>(A, 132, W1b, Wb, acc, tid, tx, ty);
    acc_finish(acc, g_zeros, tx, o);
#pragma unroll
    for (int i = 0; i < 4; i++) {
        int r = ty * 4 + i;
        if (nb + r < NN) {
            float* p = g_Q + (size_t)(nb + r) * HH + tx * 8;
            *(float4*)p       = make_float4(o[i][0], o[i][1], o[i][2], o[i][3]);
            *(float4*)(p + 4) = make_float4(o[i][4], o[i][5], o[i][6], o[i][7]);
        }
    }
    zero_acc(acc);
    gemm_tile<128>(A, 132, Wn1a, Wb, acc, tid, tx, ty);
    acc_finish(acc, bn1, tx, o);
#pragma unroll
    for (int i = 0; i < 4; i++) {
        int r = ty * 4 + i;
        if (nb + r < NN) {
            float* p = g_R + (size_t)(nb + r) * HH + tx * 8;
            *(float4*)p       = make_float4(o[i][0], o[i][1], o[i][2], o[i][3]);
            *(float4*)(p + 4) = make_float4(o[i][4], o[i][5], o[i][6], o[i][7]);
        }
    }
}

// ---------------- mma.sync machinery (512-thread edge kernels) ----------------
#define SRDB 272
#define TILEB (128 * SRDB)          // 34816
#define OFF_EH 0
#define OFF_EL TILEB
#define OFF_XH (2 * TILEB)
#define OFF_XL (3 * TILEB)
#define OFF_WH (4 * TILEB)
#define OFF_WL (5 * TILEB)
#define OFF_RED (6 * TILEB)
#define SM_EL_TOTAL (6 * TILEB + 4096)   // 212992

#define ENC_AUX (4 * TILEB)
#define SM_EENC (4 * TILEB + 4096 + 1024)  // 144384

static __device__ __forceinline__ uint32_t smem_u32(const void* p) {
    uint32_t a;
    asm("{ .reg .u64 t; cvta.to.shared.u64 t, %1; cvt.u32.u64 %0, t; }"
        : "=r"(a) : "l"(p));
    return a;
}

// 512-thread tile stage: thread -> (row = tid>>2, quarter = tid&3), 4 x 16B
__device__ __forceinline__ void load_matp(char* dstS,
                                          const __nv_bfloat16* __restrict__ src, int tid) {
    int r = tid >> 2, q = tid & 3;
#pragma unroll
    for (int j = 0; j < 4; j++) {
        int c = q * 32 + j * 8;
        uint4 v = __ldg((const uint4*)(src + (size_t)r * HH + c));
        *(uint4*)(dstS + r * SRDB + c * 2) = v;
    }
}

// 16 warps: rg = w>>2 (rows 32*rg, mi<2 of 16), cg = w&3 (cols 32*cg)
__device__ __forceinline__ void gemm_pass(float acc[2][4][4], uint32_t A, uint32_t B,
                                          int lane, int rg, int cg) {
    const uint32_t la4 = (uint32_t)((lane & 15) * SRDB + (lane >> 4) * 16);
    const uint32_t lb2 = (uint32_t)((lane & 7) * SRDB + ((lane >> 3) & 1) * 16);
#pragma unroll
    for (int kb = 0; kb < 8; kb++) {
        unsigned a[2][4], b[4][2];
#pragma unroll
        for (int mi = 0; mi < 2; mi++)
            LDSM4(a[mi], A + (32 * rg + 16 * mi) * SRDB + kb * 32 + la4);
#pragma unroll
        for (int ni = 0; ni < 4; ni++)
            LDSM2(b[ni], B + (32 * cg + 8 * ni) * SRDB + kb * 32 + lb2);
#pragma unroll
        for (int mi = 0; mi < 2; mi++)
#pragma unroll
            for (int ni = 0; ni < 4; ni++)
                MMA_BF16(acc[mi][ni], a[mi], b[ni]);
    }
}

__device__ __forceinline__ void gemm3(float acc[2][4][4],
                                      uint32_t Ah, uint32_t Al,
                                      uint32_t Bh, uint32_t Bl,
                                      int lane, int rg, int cg) {
#pragma unroll
    for (int mi = 0; mi < 2; mi++)
#pragma unroll
        for (int ni = 0; ni < 4; ni++)
#pragma unroll
            for (int q = 0; q < 4; q++) acc[mi][ni][q] = 0.f;
    gemm_pass(acc, Ah, Bh, lane, rg, cg);
    gemm_pass(acc, Ah, Bl, lane, rg, cg);
    gemm_pass(acc, Al, Bh, lane, rg, cg);
}

// ---------------- edge encoder (tensorized) ----------------
__global__ void __launch_bounds__(512, 1)
edge_enc_tc(const float* __restrict__ ea, const float* __restrict__ ez,
            const float* __restrict__ W1, const float* __restrict__ b1,
            const float* __restrict__ b2) {
    extern __shared__ char smraw[];
    char* XHs = smraw + 0;
    char* XLs = smraw + TILEB;
    char* WHs = smraw + 2 * TILEB;
    char* WLs = smraw + 3 * TILEB;
    float* W1s = (float*)(smraw + ENC_AUX);
    float* b1s = W1s + 1024;
    float* b2s = b1s + 128;
    const int tid = threadIdx.x, lane = tid & 31, w = tid >> 5;
    const int rg = w >> 2, cg = w & 3, quad = lane >> 2, tq = lane & 3;
    const int eb = blockIdx.x * 128;
    const uint32_t sb = smem_u32(smraw);

    load_matp(WHs, g_wh + 3 * 16384, tid);
    load_matp(WLs, g_wl + 3 * 16384, tid);
    if (tid < 256)      ((float4*)W1s)[tid] = __ldg((const float4*)W1 + tid);
    else if (tid < 288) ((float4*)b1s)[tid - 256] = __ldg((const float4*)b1 + (tid - 256));
    else if (tid < 320) ((float4*)b2s)[tid - 288] = __ldg((const float4*)b2 + (tid - 288));

    const int row = tid >> 2, q = tid & 3;
    float in8[8];
    {
        const float4* pa = (const float4*)(ea + (size_t)(eb + row) * 8);
        const float4* pn = (const float4*)(ez + (size_t)(eb + row) * 8);
        float4 a0 = __ldg(pa), a1 = __ldg(pa + 1);
        float4 n0 = __ldg(pn), n1 = __ldg(pn + 1);
        in8[0] = a0.x + n0.x; in8[1] = a0.y + n0.y;
        in8[2] = a0.z + n0.z; in8[3] = a0.w + n0.w;
        in8[4] = a1.x + n1.x; in8[5] = a1.y + n1.y;
        in8[6] = a1.z + n1.z; in8[7] = a1.w + n1.w;
    }
    __syncthreads();
#pragma unroll
    for (int j = 0; j < 4; j++) {
        int c0 = j * 32 + q * 8;
        float f8[8];
#pragma unroll
        for (int cc = 0; cc < 8; cc++) {
            int c = c0 + cc;
            float a = b1s[c];
#pragma unroll
            for (int k = 0; k < 8; k++) a += in8[k] * W1s[k * 128 + c];
            f8[cc] = fmaxf(a, 0.f);
        }
        split_store8(f8, (__nv_bfloat16*)(XHs + row * SRDB + c0 * 2),
                         (__nv_bfloat16*)(XLs + row * SRDB + c0 * 2));
    }
    __syncthreads();
    float acc[2][4][4];
    gemm3(acc, sb + 0, sb + TILEB, sb + 2 * TILEB, sb + 3 * TILEB, lane, rg, cg);
#pragma unroll
    for (int mi = 0; mi < 2; mi++)
#pragma unroll
        for (int h = 0; h < 2; h++) {
            int r = 32 * rg + 16 * mi + 8 * h + quad;
#pragma unroll
            for (int ni = 0; ni < 4; ni++) {
                int C = 32 * cg + 8 * ni + 2 * tq;
                float d0 = acc[mi][ni][2 * h] + b2s[C];
                float d1 = acc[mi][ni][2 * h + 1] + b2s[C + 1];
                unsigned hh, ll; split2(d0, d1, hh, ll);
                size_t base = (size_t)(eb + r) * HH + C;
                *(unsigned*)(g_eh + base) = hh;
                *(unsigned*)(g_el + base) = ll;
            }
        }
}

// ---------------- mma.sync edge layer (512 threads, R10 scheduling) ----------------
__global__ void __launch_bounds__(512, 1)
edge_layer_tc(const float* __restrict__ be2,
              const float* __restrict__ lng, const float* __restrict__ lnb) {
    extern __shared__ char smraw[];
    char* EHs = smraw + OFF_EH;
    char* ELs = smraw + OFF_EL;
    char* XHs = smraw + OFF_XH;
    char* XLs = smraw + OFF_XL;
    char* WHs = smraw + OFF_WH;
    char* WLs = smraw + OFF_WL;
    float2* RED = (float2*)(smraw + OFF_RED);

    const int tid = threadIdx.x, lane = tid & 31, w = tid >> 5;
    const int rg = w >> 2, cg = w & 3, quad = lane >> 2, tq = lane & 3;
    const int eb = blockIdx.x * 128;
    const uint32_t sb = smem_u32(smraw);
    const uint32_t aEH = sb + OFF_EH, aEL = sb + OFF_EL;
    const uint32_t aXH = sb + OFF_XH, aXL = sb + OFF_XL;
    const uint32_t aWH = sb + OFF_WH, aWL = sb + OFF_WL;

    load_matp(EHs, g_eh + (size_t)eb * HH, tid);
    load_matp(ELs, g_el + (size_t)eb * HH, tid);
    load_matp(WHs, g_wh, tid);
    load_matp(WLs, g_wl, tid);
    __syncthreads();                                   // S0

    float acc[2][4][4];

    // ---- GEMM1: U = e @ W1c ; t1 = relu(U + P[dst] + Q[src]) -> XH/XL ----
    gemm3(acc, aEH, aEL, aWH, aWL, lane, rg, cg);
#pragma unroll
    for (int mi = 0; mi < 2; mi++) {
#pragma unroll
        for (int h = 0; h < 2; h++) {
            int row = 32 * rg + 16 * mi + 8 * h + quad;
            int dn = g_dst[eb + row], sn = g_src[eb + row];
#pragma unroll
            for (int ni = 0; ni < 4; ni++) {
                int C = 32 * cg + 8 * ni + 2 * tq;
                float d0 = acc[mi][ni][2 * h], d1 = acc[mi][ni][2 * h + 1];
                float2 p = __ldg((const float2*)(g_P + (size_t)dn * HH + C));
                float2 q = __ldg((const float2*)(g_Q + (size_t)sn * HH + C));
                float v0 = fmaxf(d0 + p.x + q.x, 0.f);
                float v1 = fmaxf(d1 + p.y + q.y, 0.f);
                unsigned hh, ll; split2(v0, v1, hh, ll);
                *(unsigned*)(XHs + row * SRDB + C * 2) = hh;
                *(unsigned*)(XLs + row * SRDB + C * 2) = ll;
            }
        }
    }
    __syncthreads();                                   // S1: gemm1 done everywhere
    load_matp(WHs, g_wh + 16384, tid);
    load_matp(WLs, g_wl + 16384, tid);
    __syncthreads();                                   // S2

    // ---- GEMM2: V = t1 @ We2 ; e_new = e + V + be2 -> XH/XL ----
    gemm3(acc, aXH, aXL, aWH, aWL, lane, rg, cg);
    __syncthreads();                                   // S3: X reads done
#pragma unroll
    for (int mi = 0; mi < 2; mi++) {
#pragma unroll
        for (int h = 0; h < 2; h++) {
            int row = 32 * rg + 16 * mi + 8 * h + quad;
#pragma unroll
            for (int ni = 0; ni < 4; ni++) {
                int C = 32 * cg + 8 * ni + 2 * tq;
                float d0 = acc[mi][ni][2 * h], d1 = acc[mi][ni][2 * h + 1];
                float2 e0 = bf2f(*(unsigned*)(EHs + row * SRDB + C * 2));
                float2 e1 = bf2f(*(unsigned*)(ELs + row * SRDB + C * 2));
                float2 bb = __ldg((const float2*)(be2 + C));
                float v0 = e0.x + e1.x + d0 + bb.x;
                float v1 = e0.y + e1.y + d1 + bb.y;
                unsigned hh, ll; split2(v0, v1, hh, ll);
                *(unsigned*)(XHs + row * SRDB + C * 2) = hh;
                *(unsigned*)(XLs + row * SRDB + C * 2) = ll;
            }
        }
    }
    load_matp(WHs, g_wh + 2 * 16384, tid);
    load_matp(WLs, g_wl + 2 * 16384, tid);
    __syncthreads();                                   // S4

    // ---- GEMM3: T = e_new @ Wn1b ; t2 = relu(T + R[dst]) ; scatter-add ----
    gemm3(acc, aXH, aXL, aWH, aWL, lane, rg, cg);
#pragma unroll
    for (int mi = 0; mi < 2; mi++) {
#pragma unroll
        for (int h = 0; h < 2; h++) {
            int row = 32 * rg + 16 * mi + 8 * h + quad;
            int dn = g_dst[eb + row];
#pragma unroll
            for (int ni = 0; ni < 4; ni++) {
                int C = 32 * cg + 8 * ni + 2 * tq;
                float d0 = acc[mi][ni][2 * h], d1 = acc[mi][ni][2 * h + 1];
                float2 rr = __ldg((const float2*)(g_R + (size_t)dn * HH + C));
                red2(g_hagg + (size_t)dn * HH + C,
                     fmaxf(d0 + rr.x, 0.f), fmaxf(d1 + rr.y, 0.f));
            }
        }
    }

    // ---- edge LN: e_out = LN(e + e_new) -> g_eh/g_el (4 threads/row) ----
    {
        int r2 = tid >> 2, q = tid & 3;
        float s = 0.f, s2 = 0.f;
#pragma unroll
        for (int j = 0; j < 4; j++) {
            int c = q * 32 + j * 8;
            uint4 aH = *(uint4*)(EHs + r2 * SRDB + c * 2);
            uint4 aL = *(uint4*)(ELs + r2 * SRDB + c * 2);
            uint4 xH = *(uint4*)(XHs + r2 * SRDB + c * 2);
            uint4 xL = *(uint4*)(XLs + r2 * SRDB + c * 2);
            unsigned au[4] = {aH.x, aH.y, aH.z, aH.w};
            unsigned bu[4] = {aL.x, aL.y, aL.z, aL.w};
            unsigned cu[4] = {xH.x, xH.y, xH.z, xH.w};
            unsigned du[4] = {xL.x, xL.y, xL.z, xL.w};
#pragma unroll
            for (int t = 0; t < 4; t++) {
                float2 a = bf2f(au[t]), b = bf2f(bu[t]);
                float2 cc = bf2f(cu[t]), d = bf2f(du[t]);
                float v0 = a.x + b.x + cc.x + d.x;
                float v1 = a.y + b.y + cc.y + d.y;
                s += v0 + v1; s2 += v0 * v0 + v1 * v1;
            }
        }
        RED[tid] = make_float2(s, s2);
        __syncthreads();                               // S5 (LN internal)
        float2 p0 = RED[r2 * 4 + 0], p1 = RED[r2 * 4 + 1];
        float2 p2 = RED[r2 * 4 + 2], p3 = RED[r2 * 4 + 3];
        float sum = p0.x + p1.x + p2.x + p3.x;
        float sq  = p0.y + p1.y + p2.y + p3.y;
        float m = sum * (1.f / HH);
        float var = sq * (1.f / HH) - m * m;
        float inv = rsqrtf(var + 1e-5f);
#pragma unroll
        for (int j = 0; j < 4; j++) {
            int c = q * 32 + j * 8;
            uint4 aH = *(uint4*)(EHs + r2 * SRDB + c * 2);
            uint4 aL = *(uint4*)(ELs + r2 * SRDB + c * 2);
            uint4 xH = *(uint4*)(XHs + r2 * SRDB + c * 2);
            uint4 xL = *(uint4*)(XLs + r2 * SRDB + c * 2);
            unsigned au[4] = {aH.x, aH.y, aH.z, aH.w};
            unsigned bu[4] = {aL.x, aL.y, aL.z, aL.w};
            unsigned cu[4] = {xH.x, xH.y, xH.z, xH.w};
            unsigned du[4] = {xL.x, xL.y, xL.z, xL.w};
            float4 g0 = __ldg((const float4*)(lng + c));
            float4 g1 = __ldg((const float4*)(lng + c) + 1);
            float4 b0 = __ldg((const float4*)(lnb + c));
            float4 b1 = __ldg((const float4*)(lnb + c) + 1);
            float g8[8] = {g0.x, g0.y, g0.z, g0.w, g1.x, g1.y, g1.z, g1.w};
            float b8[8] = {b0.x, b0.y, b0.z, b0.w, b1.x, b1.y, b1.z, b1.w};
            unsigned oh[4], ol[4];
#pragma unroll
            for (int t = 0; t < 4; t++) {
                float2 a = bf2f(au[t]), b = bf2f(bu[t]);
                float2 cc = bf2f(cu[t]), d = bf2f(du[t]);
                float f0 = ((a.x + b.x + cc.x + d.x) - m) * inv * g8[2 * t] + b8[2 * t];
                float f1 = ((a.y + b.y + cc.y + d.y) - m) * inv * g8[2 * t + 1] + b8[2 * t + 1];
                split2(f0, f1, oh[t], ol[t]);
            }
            size_t gbase = (size_t)(eb + r2) * HH + c;
            *(uint4*)(g_eh + gbase) = make_uint4(oh[0], oh[1], oh[2], oh[3]);
            *(uint4*)(g_el + gbase) = make_uint4(ol[0], ol[1], ol[2], ol[3]);
        }
    }
}

// ---------------- fused node post(l) + pre(l+1) ----------------
__global__ void __launch_bounds__(256, 2)
node_fuse_kernel(const float* __restrict__ Wn2, const float* __restrict__ bn2,
                 const float* __restrict__ lg, const float* __restrict__ lb,
                 const float* __restrict__ W1a, const float* __restrict__ W1b,
                 const float* __restrict__ Wn1a,
                 const float* __restrict__ b1, const float* __restrict__ bn1) {
    extern __shared__ float sm[];
    float* A  = sm;
    float* Wb = sm + 64 * 132;
    const int tid = threadIdx.x, tx = tid & 15, ty = tid >> 4;
    const int nb = blockIdx.x * 64;
#pragma unroll 1
    for (int t = 0; t < 8; t++) {
        int idx = tid + t * 256;
        int r = idx >> 5, c4 = idx & 31;
        float4 v = make_float4(0.f, 0.f, 0.f, 0.f);
        if (nb + r < NN) v = *(const float4*)(g_hagg + (size_t)(nb + r) * HH + (c4 << 2));
        *(float4*)(A + r * 132 + (c4 << 2)) = v;
    }
    __syncthreads();
    u64 acc[16]; float o[4][8];
    zero_acc(acc);
    gemm_tile<128>(A, 132, Wn2, Wb, acc, tid, tx, ty);
    acc_finish(acc, g_zeros, tx, o);

    float4 bn0 = __ldg((const float4*)(bn2 + tx * 8));
    float4 bn1v = __ldg((const float4*)(bn2 + tx * 8) + 1);
    float4 lg0 = __ldg((const float4*)(lg + tx * 8));
    float4 lg1 = __ldg((const float4*)(lg + tx * 8) + 1);
    float4 lb0 = __ldg((const float4*)(lb + tx * 8));
    float4 lb1 = __ldg((const float4*)(lb + tx * 8) + 1);

#pragma unroll
    for (int i = 0; i < 4; i++) {
        int gi = nb + ty * 4 + i;
        if (gi < NN) {
            float deg = g_deg[gi];
            const float* hp = g_h + (size_t)gi * HH + tx * 8;
            float bnv[8] = {bn0.x, bn0.y, bn0.z, bn0.w, bn1v.x, bn1v.y, bn1v.z, bn1v.w};
            float v[8];
#pragma unroll
            for (int j = 0; j < 8; j++)
                v[j] = hp[j] * (1.f + deg) + o[i][j] + deg * bnv[j];
            float s = 0.f;
#pragma unroll
            for (int j = 0; j < 8; j++) s += v[j];
            s += __shfl_xor_sync(0xffffffffu, s, 1);
            s += __shfl_xor_sync(0xffffffffu, s, 2);
            s += __shfl_xor_sync(0xffffffffu, s, 4);
            s += __shfl_xor_sync(0xffffffffu, s, 8);
            float m = s * (1.f / HH);
            float s2 = 0.f;
#pragma unroll
            for (int j = 0; j < 8; j++) { float d = v[j] - m; s2 += d * d; }
            s2 += __shfl_xor_sync(0xffffffffu, s2, 1);
            s2 += __shfl_xor_sync(0xffffffffu, s2, 2);
            s2 += __shfl_xor_sync(0xffffffffu, s2, 4);
            s2 += __shfl_xor_sync(0xffffffffu, s2, 8);
            float inv = rsqrtf(s2 * (1.f / HH) + 1e-5f);
            float gv[8] = {lg0.x, lg0.y, lg0.z, lg0.w, lg1.x, lg1.y, lg1.z, lg1.w};
            float bv[8] = {lb0.x, lb0.y, lb0.z, lb0.w, lb1.x, lb1.y, lb1.z, lb1.w};
            float* po = g_h + (size_t)gi * HH + tx * 8;
            float* pa = A + (ty * 4 + i) * 132 + tx * 8;
#pragma unroll
            for (int j = 0; j < 8; j++) {
                float hn = (v[j] - m) * inv * gv[j] + bv[j];
                po[j] = hn;
                pa[j] = hn;
            }
            float4 z = make_float4(0.f, 0.f, 0.f, 0.f);
            float4* pz = (float4*)(g_hagg + (size_t)gi * HH + tx * 8);
            pz[0] = z; pz[1] = z;
        }
    }
    // pre(l+1): P, Q, R from h_new already in A (gemm_tile's first sync orders A writes)
    zero_acc(acc);
    gemm_tile<128>(A, 132, W1a, Wb, acc, tid, tx, ty);
    acc_finish(acc, b1, tx, o);
#pragma unroll
    for (int i = 0; i < 4; i++) {
        int r = ty * 4 + i;
        if (nb + r < NN) {
            float* p = g_P + (size_t)(nb + r) * HH + tx * 8;
            *(float4*)p       = make_float4(o[i][0], o[i][1], o[i][2], o[i][3]);
            *(float4*)(p + 4) = make_float4(o[i][4], o[i][5], o[i][6], o[i][7]);
        }
    }
    zero_acc(acc);
    gemm_tile<128>(A, 132, W1b, Wb, acc, tid, tx, ty);
    acc_finish(acc, g_zeros, tx, o);
#pragma unroll
    for (int i = 0; i < 4; i++) {
        int r = ty * 4 + i;
        if (nb + r < NN) {
            float* p = g_Q + (size_t)(nb + r) * HH + tx * 8;
            *(float4*)p       = make_float4(o[i][0], o[i][1], o[i][2], o[i][3]);
            *(float4*)(p + 4) = make_float4(o[i][4], o[i][5], o[i][6], o[i][7]);
        }
    }
    zero_acc(acc);
    gemm_tile<128>(A, 132, Wn1a, Wb, acc, tid, tx, ty);
    acc_finish(acc, bn1, tx, o);
#pragma unroll
    for (int i = 0; i < 4; i++) {
        int r = ty * 4 + i;
        if (nb + r < NN) {
            float* p = g_R + (size_t)(nb + r) * HH + tx * 8;
            *(float4*)p       = make_float4(o[i][0], o[i][1], o[i][2], o[i][3]);
            *(float4*)(p + 4) = make_float4(o[i][4], o[i][5], o[i][6], o[i][7]);
        }
    }
}

__global__ void __launch_bounds__(256, 2)
decoder_kernel(const float* __restrict__ W1, const float* __restrict__ b1,
               const float* __restrict__ W2, const float* __restrict__ b2,
               const float* __restrict__ nz, float* __restrict__ out) {
    extern __shared__ float sm[];
    float* A   = sm;
    float* hid = sm + 64 * 132;
    float* Wb  = hid + 64 * 132;
    float* W2s = Wb + 2 * 32 * HH;
    const int tid = threadIdx.x, tx = tid & 15, ty = tid >> 4;
    const int nb = blockIdx.x * 64;
#pragma unroll 1
    for (int t = 0; t < 8; t++) {
        int idx = tid + t * 256;
        int r = idx >> 5, c4 = idx & 31;
        float4 v = make_float4(0.f, 0.f, 0.f, 0.f);
        if (nb + r < NN) v = __ldg((const float4*)(g_h + (size_t)(nb + r) * HH) + c4);
        *(float4*)(A + r * 132 + (c4 << 2)) = v;
    }
    if (tid < 256) W2s[tid] = __ldg(W2 + tid);
    __syncthreads();
    u64 acc[16]; float o[4][8];
    zero_acc(acc);
    gemm_tile<128>(A, 132, W1, Wb, acc, tid, tx, ty);
    acc_finish(acc, b1, tx, o);
#pragma unroll
    for (int i = 0; i < 4; i++)
#pragma unroll
        for (int j = 0; j < 8; j++)
            hid[(ty * 4 + i) * 132 + tx * 8 + j] = fmaxf(o[i][j], 0.f);
    __syncthreads();
    if (tid < 128) {
        int r = tid >> 1, c = tid & 1;
        if (nb + r < NN) {
            float s = 0.f;
            const float* hr = hid + r * 132;
#pragma unroll 8
            for (int k = 0; k < 128; k++) s += hr[k] * W2s[k * 2 + c];
            out[(size_t)(nb + r) * 2 + c] = s + __ldg(b2 + c)
                - __ldg(nz + (size_t)(nb + r) * 16 + c);
        }
    }
}

extern "C" void kernel_launch(void* const* d_in, const int* in_sizes, int n_in,
                              void* d_out, int out_size) {
    const float* x    = (const float*)d_in[0];
    const float* ea   = (const float*)d_in[1];
    const void*  eidx = d_in[2];
    const float* nz   = (const float*)d_in[3];
    const float* ez   = (const float*)d_in[4];
    const float* ne_w1 = (const float*)d_in[5],  *ne_b1 = (const float*)d_in[6];
    const float* ne_w2 = (const float*)d_in[7],  *ne_b2 = (const float*)d_in[8];
    const float* ee_w1 = (const float*)d_in[9],  *ee_b1 = (const float*)d_in[10];
    const float* ee_w2 = (const float*)d_in[11], *ee_b2 = (const float*)d_in[12];
    const float* ge_w1 = (const float*)d_in[13], *ge_b1 = (const float*)d_in[14];
    const float* ge_w2 = (const float*)d_in[15], *ge_b2 = (const float*)d_in[16];
    const float* gn_w1 = (const float*)d_in[17], *gn_b1 = (const float*)d_in[18];
    const float* gn_w2 = (const float*)d_in[19], *gn_b2 = (const float*)d_in[20];
    const float* xlg = (const float*)d_in[21], *xlb = (const float*)d_in[22];
    const float* elg = (const float*)d_in[23], *elb = (const float*)d_in[24];
    const float* d_w1 = (const float*)d_in[25], *d_b1 = (const float*)d_in[26];
    const float* d_w2 = (const float*)d_in[27], *d_b2 = (const float*)d_in[28];
    float* out = (float*)d_out;

    const int SM_NE  = (64 * 20 + 64 * 132 + 2 * 32 * HH) * 4;
    const int SM_NP  = (64 * 132 + 2 * 32 * HH) * 4;
    const int SM_DEC = (2 * 64 * 132 + 2 * 32 * HH + 256) * 4;
    cudaFuncSetAttribute(node_enc_kernel,  cudaFuncAttributeMaxDynamicSharedMemorySize, SM_NE);
    cudaFuncSetAttribute(edge_enc_tc,      cudaFuncAttributeMaxDynamicSharedMemorySize, SM_EENC);
    cudaFuncSetAttribute(node_pre_kernel,  cudaFuncAttributeMaxDynamicSharedMemorySize, SM_NP);
    cudaFuncSetAttribute(edge_layer_tc,    cudaFuncAttributeMaxDynamicSharedMemorySize, SM_EL_TOTAL);
    cudaFuncSetAttribute(node_fuse_kernel, cudaFuncAttributeMaxDynamicSharedMemorySize, SM_NP);
    cudaFuncSetAttribute(decoder_kernel,   cudaFuncAttributeMaxDynamicSharedMemorySize, SM_DEC);

    const float* W1a  = ge_w1;
    const float* W1b  = ge_w1 + 128 * HH;
    const float* W1c  = ge_w1 + 256 * HH;
    const float* Wn1a = gn_w1;
    const float* Wn1b = gn_w1 + 128 * HH;

    detect_idx_kernel<<<1, 32>>>((const int*)eidx);
    zero_misc_kernel<<<(NN * HH / 4) / 256, 256>>>();
    convert_idx_kernel<<<(EE + 255) / 256, 256>>>(eidx);
    prep_w_kernel<<<(4 * HH * HH + 255) / 256, 256>>>(W1c, ge_w2, Wn1b, ee_w2);

    node_enc_kernel<<<(NN + 63) / 64, 256, SM_NE>>>(x, nz, ne_w1, ne_b1, ne_w2, ne_b2);
    edge_enc_tc<<<EE / 128, 512, SM_EENC>>>(ea, ez, ee_w1, ee_b1, ee_b2);
    node_pre_kernel<<<(NN + 63) / 64, 256, SM_NP>>>(W1a, W1b, Wn1a, ge_b1, gn_b1);

    for (int l = 0; l < LL; l++) {
        edge_layer_tc<<<EE / 128, 512, SM_EL_TOTAL>>>(ge_b2, elg + l * HH, elb + l * HH);
        node_fuse_kernel<<<(NN + 63) / 64, 256, SM_NP>>>(gn_w2, gn_b2,
                                                         xlg + l * HH, xlb + l * HH,
                                                         W1a, W1b, Wn1a, ge_b1, gn_b1);
    }

    decoder_kernel<<<(NN + 63) / 64, 256, SM_DEC>>>(d_w1, d_b1, d_w2, d_b2, nz, out);
}